// round 2
// baseline (speedup 1.0000x reference)
#include <cuda_runtime.h>
#include <math.h>

// Problem constants (fixed by the reference)
#define GAMMA   0.001f
#define DIM     512
#define NTEST   8192
#define NTRAIN  8192
#define NOUT    16

// Tiling
#define BM      128
#define BN      128
#define KT      16
#define KSPLIT  4
#define JTILES  (NTRAIN / KSPLIT / BN)   // 16

// Scratch (device globals — no allocation allowed)
__device__ float g_xs[NTEST];                 // exp(-gamma * ||x_i||^2)
__device__ float g_alpha_s[NTRAIN * NOUT];    // alpha[j][o] * exp(-gamma * ||y_j||^2)

// ---------------------------------------------------------------------------
// Precompute row norms: fold exp(-gamma*||y||^2) into alpha; stash exp(-gamma*||x||^2)
// One block (128 threads) per row; 512 floats = 128 float4 loads.
// ---------------------------------------------------------------------------
__global__ void precompute_kernel(const float* __restrict__ X,
                                  const float* __restrict__ TX,
                                  const float* __restrict__ alpha) {
    const int row = blockIdx.x;                 // 0 .. NTEST+NTRAIN-1
    const bool is_train = (row >= NTEST);
    const float* base = is_train ? (TX + (size_t)(row - NTEST) * DIM)
                                 : (X  + (size_t)row * DIM);
    float4 v = ((const float4*)base)[threadIdx.x];
    float s = v.x * v.x + v.y * v.y + v.z * v.z + v.w * v.w;
    #pragma unroll
    for (int off = 16; off > 0; off >>= 1)
        s += __shfl_down_sync(0xffffffffu, s, off);
    __shared__ float red[4];
    if ((threadIdx.x & 31) == 0) red[threadIdx.x >> 5] = s;
    __syncthreads();
    if (threadIdx.x < NOUT) {
        float tot = red[0] + red[1] + red[2] + red[3];
        float e = __expf(-GAMMA * tot);
        if (is_train) {
            int j = row - NTEST;
            g_alpha_s[j * NOUT + threadIdx.x] = alpha[j * NOUT + threadIdx.x] * e;
        } else if (threadIdx.x == 0) {
            g_xs[row] = e;
        }
    }
}

// ---------------------------------------------------------------------------
// Main fused kernel:
//   per block: BM test rows x (JTILES * BN) train cols, K-split over train.
//   For each 128x128 tile: C = X_tile @ Y_tile^T (fp32, 8x8 microtiles),
//   W = exp(2*gamma*C) staged in SMEM (two 64-col halves), then
//   acc[row][o] += W @ alpha_scaled_tile. Final: atomicAdd(out, xs[row]*acc).
// ---------------------------------------------------------------------------
__global__ __launch_bounds__(256, 2)
void rbf_main_kernel(const float* __restrict__ X,
                     const float* __restrict__ TX,
                     float* __restrict__ out) {
    // Union region: main loop uses [Xs (KT*BM) | Ys (KT*BN)] = 4096 floats;
    // epilogue uses Ws[BM][65] = 8320 floats. 33.3 KB.
    __shared__ float smem[BM * 65];
    __shared__ float Asm[BN][NOUT];   // scaled alpha tile, 8 KB

    float* Xs = smem;                 // [KT][BM]
    float* Ys = smem + KT * BM;       // [KT][BN]
    float* Ws = smem;                 // [BM][65]

    const int tid  = threadIdx.x;
    const int tm   = tid >> 4;        // 0..15 (row group)
    const int tn   = tid & 15;        // 0..15 (col group)
    const int row0 = blockIdx.x * BM;
    const int erow = tid & 127;            // epilogue row
    const int eog  = (tid >> 7) * 8;       // epilogue out-group: 0 or 8

    float acc[8];
    #pragma unroll
    for (int u = 0; u < 8; u++) acc[u] = 0.0f;

    for (int jt = 0; jt < JTILES; jt++) {
        const int j0 = blockIdx.y * (JTILES * BN) + jt * BN;

        __syncthreads();  // previous tile's Asm readers done
        {   // load scaled-alpha tile: 512 float4
            const float4* src = (const float4*)(g_alpha_s + (size_t)j0 * NOUT);
            float4* dst = (float4*)&Asm[0][0];
            dst[tid]        = src[tid];
            dst[tid + 256]  = src[tid + 256];
        }

        float c[8][8];
        #pragma unroll
        for (int r = 0; r < 8; r++)
            #pragma unroll
            for (int s = 0; s < 8; s++) c[r][s] = 0.0f;

        for (int kb = 0; kb < DIM; kb += KT) {
            __syncthreads();  // previous chunk / epilogue reads done
            #pragma unroll
            for (int i = 0; i < 2; i++) {
                int q  = tid + i * 256;     // 0..511
                int m  = q >> 2;            // 0..127
                int kq = (q & 3) * 4;       // 0,4,8,12
                float4 vx = *(const float4*)&X [(size_t)(row0 + m) * DIM + kb + kq];
                Xs[(kq + 0) * BM + m] = vx.x;
                Xs[(kq + 1) * BM + m] = vx.y;
                Xs[(kq + 2) * BM + m] = vx.z;
                Xs[(kq + 3) * BM + m] = vx.w;
                float4 vy = *(const float4*)&TX[(size_t)(j0 + m) * DIM + kb + kq];
                Ys[(kq + 0) * BN + m] = vy.x;
                Ys[(kq + 1) * BN + m] = vy.y;
                Ys[(kq + 2) * BN + m] = vy.z;
                Ys[(kq + 3) * BN + m] = vy.w;
            }
            __syncthreads();
            #pragma unroll
            for (int k = 0; k < KT; k++) {
                float a[8], b[8];
                *(float4*)&a[0] = *(const float4*)&Xs[k * BM + tm * 8];
                *(float4*)&a[4] = *(const float4*)&Xs[k * BM + tm * 8 + 4];
                *(float4*)&b[0] = *(const float4*)&Ys[k * BN + tn * 8];
                *(float4*)&b[4] = *(const float4*)&Ys[k * BN + tn * 8 + 4];
                #pragma unroll
                for (int r = 0; r < 8; r++)
                    #pragma unroll
                    for (int s = 0; s < 8; s++)
                        c[r][s] = fmaf(a[r], b[s], c[r][s]);
            }
        }

        // Epilogue: W = exp(2*gamma*C), acc += W @ Asm. Two 64-col halves
        // so Ws fits the union region.
        #pragma unroll
        for (int half = 0; half < 2; half++) {
            __syncthreads();  // main-loop smem reads (or prior half reads) done
            if ((tn >> 3) == half) {
                int c0 = (tn & 7) * 8;
                #pragma unroll
                for (int r = 0; r < 8; r++)
                    #pragma unroll
                    for (int s = 0; s < 8; s++)
                        Ws[(tm * 8 + r) * 65 + c0 + s] =
                            __expf(c[r][s] * (2.0f * GAMMA));
            }
            __syncthreads();
            #pragma unroll
            for (int j = 0; j < 64; j++) {
                float w = Ws[erow * 65 + j];
                const float* ar = &Asm[half * 64 + j][eog];
                float4 a0 = *(const float4*)&ar[0];
                float4 a1 = *(const float4*)&ar[4];
                acc[0] = fmaf(w, a0.x, acc[0]);
                acc[1] = fmaf(w, a0.y, acc[1]);
                acc[2] = fmaf(w, a0.z, acc[2]);
                acc[3] = fmaf(w, a0.w, acc[3]);
                acc[4] = fmaf(w, a1.x, acc[4]);
                acc[5] = fmaf(w, a1.y, acc[5]);
                acc[6] = fmaf(w, a1.z, acc[6]);
                acc[7] = fmaf(w, a1.w, acc[7]);
            }
        }
    }

    const float sc = g_xs[row0 + erow];
    #pragma unroll
    for (int u = 0; u < 8; u++)
        atomicAdd(&out[(size_t)(row0 + erow) * NOUT + eog + u], acc[u] * sc);
}

// ---------------------------------------------------------------------------
extern "C" void kernel_launch(void* const* d_in, const int* in_sizes, int n_in,
                              void* d_out, int out_size) {
    const float* X     = (const float*)d_in[0];   // [8192, 512]
    const float* TX    = (const float*)d_in[1];   // [8192, 512]
    const float* alpha = (const float*)d_in[2];   // [8192, 16]
    float* out = (float*)d_out;                   // [8192, 16]

    cudaMemsetAsync(out, 0, (size_t)out_size * sizeof(float), 0);
    precompute_kernel<<<NTEST + NTRAIN, 128>>>(X, TX, alpha);
    rbf_main_kernel<<<dim3(NTEST / BM, KSPLIT), 256>>>(X, TX, out);
}

// round 4
// speedup vs baseline: 6.1394x; 6.1394x over previous
#include <cuda_runtime.h>
#include <cuda_bf16.h>
#include <stdint.h>

// Problem constants
#define GAMMA   0.001f
#define DIM     512
#define NTEST   8192
#define NTRAIN  8192
#define NOUT    16

// Tiling
#define BM      128
#define BN      128
#define KT      32                  // bf16 K per chunk
#define KCHUNKS (DIM / KT)          // 16
#define KSPLIT  16                  // grid.y
#define JTILES  (NTRAIN / KSPLIT / BN)   // 4

// SMEM layout (dynamic, 1024-aligned base)
// stage st (st=0,1): A at st*20480 (128 rows * 80B), B at st*20480 + 10240
// Ws (epilogue) reuses [0, 33280)
#define STAGE_BYTES 20480
#define OFF_ASM     40960           // alpha tile: 128 x 16 f32 = 8192B
#define SMEM_BYTES  (OFF_ASM + 8192)

// Device scratch
__device__ __nv_bfloat16 g_Xb[NTEST * DIM];
__device__ __nv_bfloat16 g_Yb[NTRAIN * DIM];
__device__ float g_xs[NTEST];           // exp(-gamma*||x||^2)
__device__ float g_as[NTRAIN * NOUT];   // alpha * exp(-gamma*||y||^2)

// ---------------------------------------------------------------------------
__device__ __forceinline__ uint32_t smem_u32(const void* p) {
    uint32_t a;
    asm("{ .reg .u64 t; cvta.to.shared.u64 t, %1; cvt.u32.u64 %0, t; }"
        : "=r"(a) : "l"(p));
    return a;
}
__device__ __forceinline__ void cp16(uint32_t dst, const void* src) {
    asm volatile("cp.async.cg.shared.global [%0], [%1], 16;"
                 :: "r"(dst), "l"(src));
}
#define CP_COMMIT() asm volatile("cp.async.commit_group;" ::: "memory")
#define CP_WAIT(n)  asm volatile("cp.async.wait_group %0;" :: "n"(n) : "memory")

#define LDMX4(r, addr) \
    asm volatile("ldmatrix.sync.aligned.m8n8.x4.shared.b16 {%0,%1,%2,%3}, [%4];" \
        : "=r"((r)[0]), "=r"((r)[1]), "=r"((r)[2]), "=r"((r)[3]) : "r"(addr))

#define MMA16816(c, a, b0, b1) \
    asm volatile("mma.sync.aligned.m16n8k16.row.col.f32.bf16.bf16.f32 " \
        "{%0,%1,%2,%3}, {%4,%5,%6,%7}, {%8,%9}, {%0,%1,%2,%3};" \
        : "+f"((c)[0]), "+f"((c)[1]), "+f"((c)[2]), "+f"((c)[3]) \
        : "r"((a)[0]), "r"((a)[1]), "r"((a)[2]), "r"((a)[3]), "r"(b0), "r"(b1))

// ---------------------------------------------------------------------------
// Prep: fp32 -> bf16 + norm folding. 128 threads per row.
// ---------------------------------------------------------------------------
__global__ void prep_kernel(const float* __restrict__ X,
                            const float* __restrict__ TX,
                            const float* __restrict__ alpha) {
    const int row = blockIdx.x;
    const bool train = (row >= NTEST);
    const int r = train ? row - NTEST : row;
    const float* src = train ? TX + (size_t)r * DIM : X + (size_t)r * DIM;
    __nv_bfloat16* dst = train ? g_Yb + (size_t)r * DIM : g_Xb + (size_t)r * DIM;

    float4 v = ((const float4*)src)[threadIdx.x];
    __nv_bfloat162* d2 = (__nv_bfloat162*)dst;
    d2[threadIdx.x * 2]     = __floats2bfloat162_rn(v.x, v.y);
    d2[threadIdx.x * 2 + 1] = __floats2bfloat162_rn(v.z, v.w);

    float s = v.x * v.x + v.y * v.y + v.z * v.z + v.w * v.w;
    #pragma unroll
    for (int off = 16; off > 0; off >>= 1)
        s += __shfl_down_sync(0xffffffffu, s, off);
    __shared__ float red[4];
    if ((threadIdx.x & 31) == 0) red[threadIdx.x >> 5] = s;
    __syncthreads();
    if (threadIdx.x < NOUT) {
        float e = __expf(-GAMMA * (red[0] + red[1] + red[2] + red[3]));
        if (train)
            g_as[r * NOUT + threadIdx.x] = alpha[r * NOUT + threadIdx.x] * e;
        else if (threadIdx.x == 0)
            g_xs[r] = e;
    }
}

// ---------------------------------------------------------------------------
// Main kernel: bf16 mma.sync GEMM tile (128x128, K=512) + fused epilogue.
// 8 warps: warp_m = wid&1 (2), warp_n = wid>>1 (4); warp tile 64x32.
// ---------------------------------------------------------------------------
__global__ __launch_bounds__(256, 2)
void rbf_hmma_kernel(float* __restrict__ out) {
    extern __shared__ __align__(1024) uint8_t smem[];
    const uint32_t sb = smem_u32(smem);

    const int tid    = threadIdx.x;
    const int lane   = tid & 31;
    const int wid    = tid >> 5;
    const int warp_m = wid & 1;
    const int warp_n = wid >> 1;
    const int row0   = blockIdx.x * BM;

    // Per-lane ldmatrix byte offsets within a stage
    const uint32_t aoff =
        (uint32_t)(warp_m * 64 + ((lane >> 3) & 1) * 8 + (lane & 7)) * 80
        + (uint32_t)(lane >> 4) * 16;                       // (lane>>4)*8 cols *2B
    const uint32_t boff = 10240 +
        (uint32_t)(warp_n * 32 + ((lane >> 4) & 1) * 8 + (lane & 7)) * 80
        + (uint32_t)((lane >> 3) & 1) * 16;

    // Per-thread cp.async source/dest indices (same pattern for A and B)
    // idx in [0,512): row = idx>>2, kg = idx&3 (16B granules of 8 bf16)
    const int erow = tid & 127;
    const int eog  = (tid >> 7) * 8;

    // Persistent output accumulators (packed f32x2)
    uint64_t accp[8];
    #pragma unroll
    for (int p = 0; p < 8; p++) accp[p] = 0ULL;

    for (int jt = 0; jt < JTILES; jt++) {
        const int j0 = (blockIdx.y * JTILES + jt) * BN;

        __syncthreads();   // prior epilogue readers of Asm/Ws done

        // Stage the scaled-alpha tile (128 x 16 f32)
        {
            float4* dst = (float4*)(smem + OFF_ASM);
            const float4* src = (const float4*)(g_as + (size_t)j0 * NOUT);
            dst[tid]       = src[tid];
            dst[tid + 256] = src[tid + 256];
        }

        // Prefetch k-chunk 0 into stage 0
        #pragma unroll
        for (int i = 0; i < 2; i++) {
            int idx = tid + i * 256;
            int r = idx >> 2, kg = idx & 3;
            cp16(sb + r * 80 + kg * 16,
                 g_Xb + (size_t)(row0 + r) * DIM + kg * 8);
            cp16(sb + 10240 + r * 80 + kg * 16,
                 g_Yb + (size_t)(j0 + r) * DIM + kg * 8);
        }
        CP_COMMIT();

        float acc[4][4][4];
        #pragma unroll
        for (int mt = 0; mt < 4; mt++)
            #pragma unroll
            for (int nt = 0; nt < 4; nt++)
                #pragma unroll
                for (int q = 0; q < 4; q++) acc[mt][nt][q] = 0.0f;

        for (int c = 0; c < KCHUNKS; c++) {
            const uint32_t stb = (uint32_t)(c & 1) * STAGE_BYTES;
            if (c + 1 < KCHUNKS) {
                const uint32_t nstb = (uint32_t)((c + 1) & 1) * STAGE_BYTES;
                const int kb = (c + 1) * KT;
                #pragma unroll
                for (int i = 0; i < 2; i++) {
                    int idx = tid + i * 256;
                    int r = idx >> 2, kg = idx & 3;
                    cp16(sb + nstb + r * 80 + kg * 16,
                         g_Xb + (size_t)(row0 + r) * DIM + kb + kg * 8);
                    cp16(sb + nstb + 10240 + r * 80 + kg * 16,
                         g_Yb + (size_t)(j0 + r) * DIM + kb + kg * 8);
                }
                CP_COMMIT();
                CP_WAIT(1);
            } else {
                CP_WAIT(0);
            }
            __syncthreads();

            #pragma unroll
            for (int ks = 0; ks < 2; ks++) {
                uint32_t af[4][4], bf[2][4];
                #pragma unroll
                for (int mt = 0; mt < 4; mt++)
                    LDMX4(af[mt], sb + stb + aoff + mt * 1280 + ks * 32);
                #pragma unroll
                for (int n2 = 0; n2 < 2; n2++)
                    LDMX4(bf[n2], sb + stb + boff + n2 * 1280 + ks * 32);
                #pragma unroll
                for (int mt = 0; mt < 4; mt++)
                    #pragma unroll
                    for (int nt = 0; nt < 4; nt++)
                        MMA16816(acc[mt][nt], af[mt],
                                 bf[nt >> 1][(nt & 1) * 2],
                                 bf[nt >> 1][(nt & 1) * 2 + 1]);
            }
            __syncthreads();
        }

        // ---------------- Epilogue: W = exp(2*gamma*C); acc += W @ alpha ----
        float* Ws = (float*)smem;                   // [128][65] reuses stages
        const float* Asm = (const float*)(smem + OFF_ASM);

        #pragma unroll
        for (int half = 0; half < 2; half++) {
            // stage memory free: mainloop done (half 0) / gemv done (half 1)
            if ((warp_n >> 1) == half) {
                const int nb = (warp_n & 1) * 32;
                #pragma unroll
                for (int mt = 0; mt < 4; mt++) {
                    const int m = warp_m * 64 + mt * 16 + (lane >> 2);
                    #pragma unroll
                    for (int nt = 0; nt < 4; nt++) {
                        const int n = nb + nt * 8 + 2 * (lane & 3);
                        Ws[m * 65 + n]           = __expf(acc[mt][nt][0] * (2.0f * GAMMA));
                        Ws[m * 65 + n + 1]       = __expf(acc[mt][nt][1] * (2.0f * GAMMA));
                        Ws[(m + 8) * 65 + n]     = __expf(acc[mt][nt][2] * (2.0f * GAMMA));
                        Ws[(m + 8) * 65 + n + 1] = __expf(acc[mt][nt][3] * (2.0f * GAMMA));
                    }
                }
            }
            __syncthreads();
            #pragma unroll
            for (int j = 0; j < 64; j++) {
                float w = Ws[erow * 65 + j];
                uint64_t wp;
                asm("mov.b64 %0, {%1, %1};" : "=l"(wp) : "r"(__float_as_uint(w)));
                const float4* ar = (const float4*)(Asm + (half * 64 + j) * NOUT + eog);
                float4 a0 = ar[0];
                float4 a1 = ar[1];
                uint64_t p0, p1, p2, p3;
                asm("mov.b64 %0, {%1, %2};" : "=l"(p0) : "f"(a0.x), "f"(a0.y));
                asm("mov.b64 %0, {%1, %2};" : "=l"(p1) : "f"(a0.z), "f"(a0.w));
                asm("mov.b64 %0, {%1, %2};" : "=l"(p2) : "f"(a1.x), "f"(a1.y));
                asm("mov.b64 %0, {%1, %2};" : "=l"(p3) : "f"(a1.z), "f"(a1.w));
                asm("fma.rn.f32x2 %0, %1, %2, %0;" : "+l"(accp[0]) : "l"(wp), "l"(p0));
                asm("fma.rn.f32x2 %0, %1, %2, %0;" : "+l"(accp[1]) : "l"(wp), "l"(p1));
                asm("fma.rn.f32x2 %0, %1, %2, %0;" : "+l"(accp[2]) : "l"(wp), "l"(p2));
                asm("fma.rn.f32x2 %0, %1, %2, %0;" : "+l"(accp[3]) : "l"(wp), "l"(p3));
            }
            __syncthreads();
            // second pass reuses accp[0..3]? No: separate halves accumulate
            // into the same 8 outputs (j ranges differ) — accp[0..3] hold
            // outputs eog..eog+7 across ALL j. Keep using accp[0..3] only.
        }
    }

    const float sc = g_xs[row0 + erow];
    float* op = out + (size_t)(row0 + erow) * NOUT + eog;
    #pragma unroll
    for (int p = 0; p < 4; p++) {
        uint32_t lo, hi;
        asm("mov.b64 {%0, %1}, %2;" : "=r"(lo), "=r"(hi) : "l"(accp[p]));
        atomicAdd(&op[p * 2],     __uint_as_float(lo) * sc);
        atomicAdd(&op[p * 2 + 1], __uint_as_float(hi) * sc);
    }
}

// ---------------------------------------------------------------------------
extern "C" void kernel_launch(void* const* d_in, const int* in_sizes, int n_in,
                              void* d_out, int out_size) {
    const float* X     = (const float*)d_in[0];
    const float* TX    = (const float*)d_in[1];
    const float* alpha = (const float*)d_in[2];
    float* out = (float*)d_out;

    cudaFuncSetAttribute(rbf_hmma_kernel,
                         cudaFuncAttributeMaxDynamicSharedMemorySize, SMEM_BYTES);

    cudaMemsetAsync(out, 0, (size_t)out_size * sizeof(float), 0);
    prep_kernel<<<NTEST + NTRAIN, 128>>>(X, TX, alpha);
    rbf_hmma_kernel<<<dim3(NTEST / BM, KSPLIT), 256, SMEM_BYTES>>>(out);
}

// round 5
// speedup vs baseline: 6.2700x; 1.0213x over previous
#include <cuda_runtime.h>
#include <cuda_bf16.h>
#include <stdint.h>

// Problem constants
#define GAMMA   0.001f
#define DIM     512
#define NTEST   8192
#define NTRAIN  8192
#define NOUT    16

// Tiling
#define BM      128
#define BN      128
#define KT      32                  // bf16 K per chunk
#define KCHUNKS (DIM / KT)          // 16
#define NSTAGE  4

// SMEM: stage = A(128 rows x 80B) + B(128 rows x 80B) = 20480B
#define STAGE_BYTES 20480
#define OFF_B       10240
#define OFF_ASM     (NSTAGE * STAGE_BYTES)   // 81920: alpha 128x16 f32 = 8KB
#define SMEM_BYTES  (OFF_ASM + 8192)         // 90112

// Device scratch
__device__ __nv_bfloat16 g_Xb[NTEST * DIM];
__device__ __nv_bfloat16 g_Yb[NTRAIN * DIM];
__device__ float g_xs[NTEST];           // exp(-gamma*||x||^2)
__device__ float g_as[NTRAIN * NOUT];   // alpha * exp(-gamma*||y||^2)

// ---------------------------------------------------------------------------
__device__ __forceinline__ uint32_t smem_u32(const void* p) {
    uint32_t a;
    asm("{ .reg .u64 t; cvta.to.shared.u64 t, %1; cvt.u32.u64 %0, t; }"
        : "=r"(a) : "l"(p));
    return a;
}
__device__ __forceinline__ void cp16(uint32_t dst, const void* src) {
    asm volatile("cp.async.cg.shared.global [%0], [%1], 16;"
                 :: "r"(dst), "l"(src));
}
#define CP_COMMIT() asm volatile("cp.async.commit_group;" ::: "memory")
#define CP_WAIT(n)  asm volatile("cp.async.wait_group %0;" :: "n"(n) : "memory")

#define LDMX4(r, addr) \
    asm volatile("ldmatrix.sync.aligned.m8n8.x4.shared.b16 {%0,%1,%2,%3}, [%4];" \
        : "=r"((r)[0]), "=r"((r)[1]), "=r"((r)[2]), "=r"((r)[3]) : "r"(addr))

#define MMA16816(c, a, b0, b1) \
    asm volatile("mma.sync.aligned.m16n8k16.row.col.f32.bf16.bf16.f32 " \
        "{%0,%1,%2,%3}, {%4,%5,%6,%7}, {%8,%9}, {%0,%1,%2,%3};" \
        : "+f"((c)[0]), "+f"((c)[1]), "+f"((c)[2]), "+f"((c)[3]) \
        : "r"((a)[0]), "r"((a)[1]), "r"((a)[2]), "r"((a)[3]), "r"(b0), "r"(b1))

// ---------------------------------------------------------------------------
// Prep: fp32 -> bf16 + norm folding. 128 threads per row.
// ---------------------------------------------------------------------------
__global__ void prep_kernel(const float* __restrict__ X,
                            const float* __restrict__ TX,
                            const float* __restrict__ alpha) {
    const int row = blockIdx.x;
    const bool train = (row >= NTEST);
    const int r = train ? row - NTEST : row;
    const float* src = train ? TX + (size_t)r * DIM : X + (size_t)r * DIM;
    __nv_bfloat16* dst = train ? g_Yb + (size_t)r * DIM : g_Xb + (size_t)r * DIM;

    float4 v = ((const float4*)src)[threadIdx.x];
    __nv_bfloat162* d2 = (__nv_bfloat162*)dst;
    d2[threadIdx.x * 2]     = __floats2bfloat162_rn(v.x, v.y);
    d2[threadIdx.x * 2 + 1] = __floats2bfloat162_rn(v.z, v.w);

    float s = v.x * v.x + v.y * v.y + v.z * v.z + v.w * v.w;
    #pragma unroll
    for (int off = 16; off > 0; off >>= 1)
        s += __shfl_down_sync(0xffffffffu, s, off);
    __shared__ float red[4];
    if ((threadIdx.x & 31) == 0) red[threadIdx.x >> 5] = s;
    __syncthreads();
    if (threadIdx.x < NOUT) {
        float e = __expf(-GAMMA * (red[0] + red[1] + red[2] + red[3]));
        if (train)
            g_as[r * NOUT + threadIdx.x] = alpha[r * NOUT + threadIdx.x] * e;
        else if (threadIdx.x == 0)
            g_xs[r] = e;
    }
}

// ---------------------------------------------------------------------------
// Main kernel: 128x128 tile, K=512, 4 warps (2x2), warp tile 64x64.
// 4-stage cp.async pipeline, one barrier per chunk, fused exp/GEMV epilogue.
// ---------------------------------------------------------------------------
__global__ __launch_bounds__(128)
void rbf_hmma_kernel(float* __restrict__ out) {
    extern __shared__ __align__(1024) uint8_t smem[];
    const uint32_t sb = smem_u32(smem);

    const int tid    = threadIdx.x;
    const int lane   = tid & 31;
    const int wid    = tid >> 5;
    const int warp_m = wid & 1;      // 0..1
    const int warp_n = wid >> 1;     // 0..1
    const int row0   = blockIdx.x * BM;
    const int j0     = blockIdx.y * BN;

    // ldmatrix per-lane byte offsets within a stage
    const uint32_t aoff =
        (uint32_t)(warp_m * 64 + ((lane >> 3) & 1) * 8 + (lane & 7)) * 80
        + (uint32_t)(lane >> 4) * 16;
    const uint32_t boff = OFF_B +
        (uint32_t)(warp_n * 64 + ((lane >> 4) & 1) * 8 + (lane & 7)) * 80
        + (uint32_t)((lane >> 3) & 1) * 16;

    // Stage the scaled-alpha tile (128 x 16 f32); visible after first barrier.
    {
        float4* dst = (float4*)(smem + OFF_ASM);
        const float4* src = (const float4*)(g_as + (size_t)j0 * NOUT);
        #pragma unroll
        for (int i = 0; i < 4; i++) dst[tid + i * 128] = src[tid + i * 128];
    }

    // Prologue: prefetch chunks 0..2 into stages 0..2
    #pragma unroll
    for (int p = 0; p < 3; p++) {
        const uint32_t stb = (uint32_t)p * STAGE_BYTES;
        const int kb = p * KT;
        #pragma unroll
        for (int i = 0; i < 4; i++) {
            int idx = tid + i * 128;
            int r = idx >> 2, kg = idx & 3;
            cp16(sb + stb + r * 80 + kg * 16,
                 g_Xb + (size_t)(row0 + r) * DIM + kb + kg * 8);
            cp16(sb + stb + OFF_B + r * 80 + kg * 16,
                 g_Yb + (size_t)(j0 + r) * DIM + kb + kg * 8);
        }
        CP_COMMIT();
    }

    float acc[4][8][4];
    #pragma unroll
    for (int mt = 0; mt < 4; mt++)
        #pragma unroll
        for (int nt = 0; nt < 8; nt++)
            #pragma unroll
            for (int q = 0; q < 4; q++) acc[mt][nt][q] = 0.0f;

    for (int c = 0; c < KCHUNKS; c++) {
        CP_WAIT(2);          // chunk c landed (3+c groups committed so far)
        __syncthreads();     // visibility + all warps done with stage (c+3)&3

        if (c + 3 < KCHUNKS) {
            const uint32_t nstb = (uint32_t)((c + 3) & 3) * STAGE_BYTES;
            const int kb = (c + 3) * KT;
            #pragma unroll
            for (int i = 0; i < 4; i++) {
                int idx = tid + i * 128;
                int r = idx >> 2, kg = idx & 3;
                cp16(sb + nstb + r * 80 + kg * 16,
                     g_Xb + (size_t)(row0 + r) * DIM + kb + kg * 8);
                cp16(sb + nstb + OFF_B + r * 80 + kg * 16,
                     g_Yb + (size_t)(j0 + r) * DIM + kb + kg * 8);
            }
        }
        CP_COMMIT();         // empty group near tail keeps CP_WAIT(2) uniform

        const uint32_t stb = (uint32_t)(c & 3) * STAGE_BYTES;
        #pragma unroll
        for (int ks = 0; ks < 2; ks++) {
            uint32_t af[4][4], bf[4][4];
            #pragma unroll
            for (int mt = 0; mt < 4; mt++)
                LDMX4(af[mt], sb + stb + aoff + mt * 1280 + ks * 32);
            #pragma unroll
            for (int nb = 0; nb < 4; nb++)
                LDMX4(bf[nb], sb + stb + boff + nb * 1280 + ks * 32);
            #pragma unroll
            for (int mt = 0; mt < 4; mt++)
                #pragma unroll
                for (int nt = 0; nt < 8; nt++)
                    MMA16816(acc[mt][nt], af[mt],
                             bf[nt >> 1][(nt & 1) * 2],
                             bf[nt >> 1][(nt & 1) * 2 + 1]);
        }
    }

    // ------------------ Epilogue: W = exp(2*gamma*C); out += W @ alpha ------
    float* Ws = (float*)smem;                     // [128][129], 66048B
    const float* Asm = (const float*)(smem + OFF_ASM);

    __syncthreads();   // all LDSM of last chunk done before overwriting stages
    #pragma unroll
    for (int mt = 0; mt < 4; mt++) {
        const int m = warp_m * 64 + mt * 16 + (lane >> 2);
        #pragma unroll
        for (int nt = 0; nt < 8; nt++) {
            const int n = warp_n * 64 + nt * 8 + 2 * (lane & 3);
            Ws[m * 129 + n]           = __expf(acc[mt][nt][0] * (2.0f * GAMMA));
            Ws[m * 129 + n + 1]       = __expf(acc[mt][nt][1] * (2.0f * GAMMA));
            Ws[(m + 8) * 129 + n]     = __expf(acc[mt][nt][2] * (2.0f * GAMMA));
            Ws[(m + 8) * 129 + n + 1] = __expf(acc[mt][nt][3] * (2.0f * GAMMA));
        }
    }
    __syncthreads();

    // GEMV: thread t owns output row t (all 16 outputs, packed f32x2).
    uint64_t accp[8];
    #pragma unroll
    for (int p = 0; p < 8; p++) accp[p] = 0ULL;

    #pragma unroll 8
    for (int j = 0; j < BN; j++) {
        float w = Ws[tid * 129 + j];
        uint64_t wp;
        asm("mov.b64 %0, {%1, %1};" : "=l"(wp) : "r"(__float_as_uint(w)));
        const float4* ar = (const float4*)(Asm + j * NOUT);
        #pragma unroll
        for (int q = 0; q < 4; q++) {
            float4 a = ar[q];
            uint64_t lo, hi;
            asm("mov.b64 %0, {%1, %2};" : "=l"(lo) : "f"(a.x), "f"(a.y));
            asm("mov.b64 %0, {%1, %2};" : "=l"(hi) : "f"(a.z), "f"(a.w));
            asm("fma.rn.f32x2 %0, %1, %2, %0;" : "+l"(accp[q * 2])     : "l"(wp), "l"(lo));
            asm("fma.rn.f32x2 %0, %1, %2, %0;" : "+l"(accp[q * 2 + 1]) : "l"(wp), "l"(hi));
        }
    }

    const float sc = g_xs[row0 + tid];
    float* op = out + (size_t)(row0 + tid) * NOUT;
    #pragma unroll
    for (int p = 0; p < 8; p++) {
        uint32_t lo, hi;
        asm("mov.b64 {%0, %1}, %2;" : "=r"(lo), "=r"(hi) : "l"(accp[p]));
        atomicAdd(&op[p * 2],     __uint_as_float(lo) * sc);
        atomicAdd(&op[p * 2 + 1], __uint_as_float(hi) * sc);
    }
}

// ---------------------------------------------------------------------------
extern "C" void kernel_launch(void* const* d_in, const int* in_sizes, int n_in,
                              void* d_out, int out_size) {
    const float* X     = (const float*)d_in[0];
    const float* TX    = (const float*)d_in[1];
    const float* alpha = (const float*)d_in[2];
    float* out = (float*)d_out;

    cudaFuncSetAttribute(rbf_hmma_kernel,
                         cudaFuncAttributeMaxDynamicSharedMemorySize, SMEM_BYTES);

    cudaMemsetAsync(out, 0, (size_t)out_size * sizeof(float), 0);
    prep_kernel<<<NTEST + NTRAIN, 128>>>(X, TX, alpha);
    rbf_hmma_kernel<<<dim3(NTEST / BM, NTRAIN / BN), 128, SMEM_BYTES>>>(out);
}

// round 6
// speedup vs baseline: 6.5662x; 1.0472x over previous
#include <cuda_runtime.h>
#include <cuda_bf16.h>
#include <stdint.h>

// Problem constants
#define GAMMA   0.001f
#define DIM     512
#define NTEST   8192
#define NTRAIN  8192
#define NOUT    16

// Tiling
#define BM      128
#define BN      128
#define KT      32                  // bf16 K per chunk
#define KCHUNKS (DIM / KT)          // 16
#define NSTAGE  3

// SMEM: stage = A(128 rows x 80B) + B(128 rows x 80B) = 20480B
#define STAGE_BYTES 20480
#define OFF_B       10240
#define OFF_ASM     (NSTAGE * STAGE_BYTES)   // 61440: alpha 128x16 f32 = 8KB
#define SMEM_BYTES  (OFF_ASM + 8192)         // 69632 -> 3 CTAs/SM

// Device scratch
__device__ __nv_bfloat16 g_Xb[NTEST * DIM];
__device__ __nv_bfloat16 g_Yb[NTRAIN * DIM];
__device__ float g_xs[NTEST];           // exp(-gamma*||x||^2)
__device__ float g_as[NTRAIN * NOUT];   // alpha * exp(-gamma*||y||^2)

// ---------------------------------------------------------------------------
__device__ __forceinline__ uint32_t smem_u32(const void* p) {
    uint32_t a;
    asm("{ .reg .u64 t; cvta.to.shared.u64 t, %1; cvt.u32.u64 %0, t; }"
        : "=r"(a) : "l"(p));
    return a;
}
__device__ __forceinline__ void cp16(uint32_t dst, const void* src) {
    asm volatile("cp.async.cg.shared.global [%0], [%1], 16;"
                 :: "r"(dst), "l"(src));
}
#define CP_COMMIT() asm volatile("cp.async.commit_group;" ::: "memory")
#define CP_WAIT(n)  asm volatile("cp.async.wait_group %0;" :: "n"(n) : "memory")

#define LDMX4(r, addr) \
    asm volatile("ldmatrix.sync.aligned.m8n8.x4.shared.b16 {%0,%1,%2,%3}, [%4];" \
        : "=r"((r)[0]), "=r"((r)[1]), "=r"((r)[2]), "=r"((r)[3]) : "r"(addr))

#define MMA16816(c, a, b0, b1) \
    asm volatile("mma.sync.aligned.m16n8k16.row.col.f32.bf16.bf16.f32 " \
        "{%0,%1,%2,%3}, {%4,%5,%6,%7}, {%8,%9}, {%0,%1,%2,%3};" \
        : "+f"((c)[0]), "+f"((c)[1]), "+f"((c)[2]), "+f"((c)[3]) \
        : "r"((a)[0]), "r"((a)[1]), "r"((a)[2]), "r"((a)[3]), "r"(b0), "r"(b1))

// ---------------------------------------------------------------------------
// Prep: fp32 -> bf16 + norm folding. 128 threads per row.
// ---------------------------------------------------------------------------
__global__ void prep_kernel(const float* __restrict__ X,
                            const float* __restrict__ TX,
                            const float* __restrict__ alpha) {
    const int row = blockIdx.x;
    const bool train = (row >= NTEST);
    const int r = train ? row - NTEST : row;
    const float* src = train ? TX + (size_t)r * DIM : X + (size_t)r * DIM;
    __nv_bfloat16* dst = train ? g_Yb + (size_t)r * DIM : g_Xb + (size_t)r * DIM;

    float4 v = ((const float4*)src)[threadIdx.x];
    __nv_bfloat162* d2 = (__nv_bfloat162*)dst;
    d2[threadIdx.x * 2]     = __floats2bfloat162_rn(v.x, v.y);
    d2[threadIdx.x * 2 + 1] = __floats2bfloat162_rn(v.z, v.w);

    float s = v.x * v.x + v.y * v.y + v.z * v.z + v.w * v.w;
    #pragma unroll
    for (int off = 16; off > 0; off >>= 1)
        s += __shfl_down_sync(0xffffffffu, s, off);
    __shared__ float red[4];
    if ((threadIdx.x & 31) == 0) red[threadIdx.x >> 5] = s;
    __syncthreads();
    if (threadIdx.x < NOUT) {
        float e = __expf(-GAMMA * (red[0] + red[1] + red[2] + red[3]));
        if (train)
            g_as[r * NOUT + threadIdx.x] = alpha[r * NOUT + threadIdx.x] * e;
        else if (threadIdx.x == 0)
            g_xs[r] = e;
    }
}

// ---------------------------------------------------------------------------
// Main kernel: 128x128 tile, K=512, 4 warps (2x2), warp tile 64x64.
// 3-stage cp.async pipeline (3 CTAs/SM), fused exp/GEMV epilogue in 2 halves.
// ---------------------------------------------------------------------------
__global__ __launch_bounds__(128, 3)
void rbf_hmma_kernel(float* __restrict__ out) {
    extern __shared__ __align__(1024) uint8_t smem[];
    const uint32_t sb = smem_u32(smem);

    const int tid    = threadIdx.x;
    const int lane   = tid & 31;
    const int wid    = tid >> 5;
    const int warp_m = wid & 1;      // 0..1
    const int warp_n = wid >> 1;     // 0..1
    const int row0   = blockIdx.x * BM;
    const int j0     = blockIdx.y * BN;

    // ldmatrix per-lane byte offsets within a stage
    const uint32_t aoff =
        (uint32_t)(warp_m * 64 + ((lane >> 3) & 1) * 8 + (lane & 7)) * 80
        + (uint32_t)(lane >> 4) * 16;
    const uint32_t boff = OFF_B +
        (uint32_t)(warp_n * 64 + ((lane >> 4) & 1) * 8 + (lane & 7)) * 80
        + (uint32_t)((lane >> 3) & 1) * 16;

    // cp.async: per-thread fixed row/granule; hoisted global byte offsets
    const int cprow = tid >> 2;          // 0..31 (+32*i)
    const int cpkg  = tid & 3;           // 16B granule
    const __nv_bfloat16* xsrc = g_Xb + (size_t)(row0 + cprow) * DIM + cpkg * 8;
    const __nv_bfloat16* ysrc = g_Yb + (size_t)(j0   + cprow) * DIM + cpkg * 8;
    const uint32_t cpdst = (uint32_t)cprow * 80 + (uint32_t)cpkg * 16;
    const uint32_t ROWSTEP = 32 * DIM;   // elements per +32 rows

    // Stage the scaled-alpha tile (128 x 16 f32); visible after first barrier.
    {
        float4* dst = (float4*)(smem + OFF_ASM);
        const float4* src = (const float4*)(g_as + (size_t)j0 * NOUT);
        #pragma unroll
        for (int i = 0; i < 4; i++) dst[tid + i * 128] = src[tid + i * 128];
    }

    // Prologue: prefetch chunks 0..1 into stages 0..1
    #pragma unroll
    for (int p = 0; p < 2; p++) {
        const uint32_t stb = (uint32_t)p * STAGE_BYTES;
        #pragma unroll
        for (int i = 0; i < 4; i++) {
            cp16(sb + stb + cpdst + i * 2560,         xsrc + i * ROWSTEP + p * KT);
            cp16(sb + stb + OFF_B + cpdst + i * 2560, ysrc + i * ROWSTEP + p * KT);
        }
        CP_COMMIT();
    }

    float acc[4][8][4];
    #pragma unroll
    for (int mt = 0; mt < 4; mt++)
        #pragma unroll
        for (int nt = 0; nt < 8; nt++)
            #pragma unroll
            for (int q = 0; q < 4; q++) acc[mt][nt][q] = 0.0f;

    for (int c = 0; c < KCHUNKS; c++) {
        CP_WAIT(1);          // chunk c landed
        __syncthreads();     // visibility + all warps done with stage (c+2)%3

        if (c + 2 < KCHUNKS) {
            const uint32_t nstb = (uint32_t)((c + 2) % 3) * STAGE_BYTES;
            const int kb = (c + 2) * KT;
            #pragma unroll
            for (int i = 0; i < 4; i++) {
                cp16(sb + nstb + cpdst + i * 2560,         xsrc + i * ROWSTEP + kb);
                cp16(sb + nstb + OFF_B + cpdst + i * 2560, ysrc + i * ROWSTEP + kb);
            }
        }
        CP_COMMIT();         // empty group at tail keeps CP_WAIT(1) uniform

        const uint32_t stb = (uint32_t)(c % 3) * STAGE_BYTES;
        #pragma unroll
        for (int ks = 0; ks < 2; ks++) {
            uint32_t af[4][4], bf[4][4];
            #pragma unroll
            for (int mt = 0; mt < 4; mt++)
                LDMX4(af[mt], sb + stb + aoff + mt * 1280 + ks * 32);
            #pragma unroll
            for (int nb = 0; nb < 4; nb++)
                LDMX4(bf[nb], sb + stb + boff + nb * 1280 + ks * 32);
            #pragma unroll
            for (int mt = 0; mt < 4; mt++)
                #pragma unroll
                for (int nt = 0; nt < 8; nt++)
                    MMA16816(acc[mt][nt], af[mt],
                             bf[nt >> 1][(nt & 1) * 2],
                             bf[nt >> 1][(nt & 1) * 2 + 1]);
        }
    }

    // ------------------ Epilogue: W = exp(2*gamma*C); out += W @ alpha ------
    // Two 64-col halves so Ws[128][65] (33.3KB) fits the 3-stage region.
    float* Ws = (float*)smem;
    const float* Asm = (const float*)(smem + OFF_ASM);

    uint64_t accp[8];
    #pragma unroll
    for (int p = 0; p < 8; p++) accp[p] = 0ULL;

    #pragma unroll
    for (int half = 0; half < 2; half++) {
        __syncthreads();   // stage LDSMs done (h0) / prior GEMV reads done (h1)
        if (warp_n == half) {
            #pragma unroll
            for (int mt = 0; mt < 4; mt++) {
                const int m = warp_m * 64 + mt * 16 + (lane >> 2);
                #pragma unroll
                for (int nt = 0; nt < 8; nt++) {
                    const int n = nt * 8 + 2 * (lane & 3);
                    Ws[m * 65 + n]           = __expf(acc[mt][nt][0] * (2.0f * GAMMA));
                    Ws[m * 65 + n + 1]       = __expf(acc[mt][nt][1] * (2.0f * GAMMA));
                    Ws[(m + 8) * 65 + n]     = __expf(acc[mt][nt][2] * (2.0f * GAMMA));
                    Ws[(m + 8) * 65 + n + 1] = __expf(acc[mt][nt][3] * (2.0f * GAMMA));
                }
            }
        }
        __syncthreads();

        #pragma unroll 8
        for (int j = 0; j < 64; j++) {
            float w = Ws[tid * 65 + j];
            uint64_t wp;
            asm("mov.b64 %0, {%1, %1};" : "=l"(wp) : "r"(__float_as_uint(w)));
            const float4* ar = (const float4*)(Asm + (half * 64 + j) * NOUT);
            #pragma unroll
            for (int q = 0; q < 4; q++) {
                float4 a = ar[q];
                uint64_t lo, hi;
                asm("mov.b64 %0, {%1, %2};" : "=l"(lo) : "f"(a.x), "f"(a.y));
                asm("mov.b64 %0, {%1, %2};" : "=l"(hi) : "f"(a.z), "f"(a.w));
                asm("fma.rn.f32x2 %0, %1, %2, %0;" : "+l"(accp[q * 2])     : "l"(wp), "l"(lo));
                asm("fma.rn.f32x2 %0, %1, %2, %0;" : "+l"(accp[q * 2 + 1]) : "l"(wp), "l"(hi));
            }
        }
    }

    const float sc = g_xs[row0 + tid];
    float* op = out + (size_t)(row0 + tid) * NOUT;
    #pragma unroll
    for (int p = 0; p < 8; p++) {
        uint32_t lo, hi;
        asm("mov.b64 {%0, %1}, %2;" : "=r"(lo), "=r"(hi) : "l"(accp[p]));
        atomicAdd(&op[p * 2],     __uint_as_float(lo) * sc);
        atomicAdd(&op[p * 2 + 1], __uint_as_float(hi) * sc);
    }
}

// ---------------------------------------------------------------------------
extern "C" void kernel_launch(void* const* d_in, const int* in_sizes, int n_in,
                              void* d_out, int out_size) {
    const float* X     = (const float*)d_in[0];
    const float* TX    = (const float*)d_in[1];
    const float* alpha = (const float*)d_in[2];
    float* out = (float*)d_out;

    cudaFuncSetAttribute(rbf_hmma_kernel,
                         cudaFuncAttributeMaxDynamicSharedMemorySize, SMEM_BYTES);

    cudaMemsetAsync(out, 0, (size_t)out_size * sizeof(float), 0);
    prep_kernel<<<NTEST + NTRAIN, 128>>>(X, TX, alpha);
    rbf_hmma_kernel<<<dim3(NTEST / BM, NTRAIN / BN), 128, SMEM_BYTES>>>(out);
}

// round 7
// speedup vs baseline: 8.7729x; 1.3361x over previous
#include <cuda_runtime.h>
#include <cuda_fp16.h>
#include <stdint.h>

// Problem constants
#define GAMMA   0.001f
#define DIM     512
#define NTEST   8192
#define NTRAIN  8192
#define NOUT    16

// Tiling
#define BM      128
#define BN      128
#define KT      32                  // fp16 K per chunk
#define KCHUNKS (DIM / KT)          // 16
#define NSTAGE  3

// SMEM: stage = A(128 rows x 80B) + B(128 rows x 80B) = 20480B
#define STAGE_BYTES 20480
#define OFF_B       10240
#define OFF_ASH     (NSTAGE * STAGE_BYTES)   // 61440: alpha fp16 128 x 48B
#define SMEM_BYTES  (OFF_ASH + 6144)         // 67584 -> 3 CTAs/SM
#define WS_PITCH    272                      // fp16 W' tile row pitch (epilogue)

// Device scratch
__device__ __half g_Xh[NTEST * DIM];
__device__ __half g_Yh[NTRAIN * DIM];
__device__ float  g_xs[NTEST];           // exp(-gamma*||x||^2)
__device__ float  g_as[NTRAIN * NOUT];   // alpha * exp(-gamma*||y||^2)
__device__ float  g_S[NOUT];             // column sums of g_as

// ---------------------------------------------------------------------------
__device__ __forceinline__ uint32_t smem_u32(const void* p) {
    uint32_t a;
    asm("{ .reg .u64 t; cvta.to.shared.u64 t, %1; cvt.u32.u64 %0, t; }"
        : "=r"(a) : "l"(p));
    return a;
}
__device__ __forceinline__ void cp16(uint32_t dst, const void* src) {
    asm volatile("cp.async.cg.shared.global [%0], [%1], 16;"
                 :: "r"(dst), "l"(src));
}
#define CP_COMMIT() asm volatile("cp.async.commit_group;" ::: "memory")
#define CP_WAIT(n)  asm volatile("cp.async.wait_group %0;" :: "n"(n) : "memory")

#define LDMX4(r, addr) \
    asm volatile("ldmatrix.sync.aligned.m8n8.x4.shared.b16 {%0,%1,%2,%3}, [%4];" \
        : "=r"((r)[0]), "=r"((r)[1]), "=r"((r)[2]), "=r"((r)[3]) : "r"(addr))

#define LDMX4T(r, addr) \
    asm volatile("ldmatrix.sync.aligned.m8n8.x4.trans.shared.b16 {%0,%1,%2,%3}, [%4];" \
        : "=r"((r)[0]), "=r"((r)[1]), "=r"((r)[2]), "=r"((r)[3]) : "r"(addr))

#define MMAF16(c, a, b0, b1) \
    asm volatile("mma.sync.aligned.m16n8k16.row.col.f32.f16.f16.f32 " \
        "{%0,%1,%2,%3}, {%4,%5,%6,%7}, {%8,%9}, {%0,%1,%2,%3};" \
        : "+f"((c)[0]), "+f"((c)[1]), "+f"((c)[2]), "+f"((c)[3]) \
        : "r"((a)[0]), "r"((a)[1]), "r"((a)[2]), "r"((a)[3]), "r"(b0), "r"(b1))

// ---------------------------------------------------------------------------
__global__ void zero_s_kernel() {
    if (threadIdx.x < NOUT) g_S[threadIdx.x] = 0.0f;
}

// Prep: fp32 -> fp16 + norm folding + global alpha column sums.
__global__ void prep_kernel(const float* __restrict__ X,
                            const float* __restrict__ TX,
                            const float* __restrict__ alpha) {
    const int row = blockIdx.x;
    const bool train = (row >= NTEST);
    const int r = train ? row - NTEST : row;
    const float* src = train ? TX + (size_t)r * DIM : X + (size_t)r * DIM;
    __half* dst = train ? g_Yh + (size_t)r * DIM : g_Xh + (size_t)r * DIM;

    float4 v = ((const float4*)src)[threadIdx.x];
    __half2* d2 = (__half2*)dst;
    d2[threadIdx.x * 2]     = __floats2half2_rn(v.x, v.y);
    d2[threadIdx.x * 2 + 1] = __floats2half2_rn(v.z, v.w);

    float s = v.x * v.x + v.y * v.y + v.z * v.z + v.w * v.w;
    #pragma unroll
    for (int off = 16; off > 0; off >>= 1)
        s += __shfl_down_sync(0xffffffffu, s, off);
    __shared__ float red[4];
    if ((threadIdx.x & 31) == 0) red[threadIdx.x >> 5] = s;
    __syncthreads();
    if (threadIdx.x < NOUT) {
        float e = __expf(-GAMMA * (red[0] + red[1] + red[2] + red[3]));
        if (train) {
            float val = alpha[r * NOUT + threadIdx.x] * e;
            g_as[r * NOUT + threadIdx.x] = val;
            atomicAdd(&g_S[threadIdx.x], val);
        } else if (threadIdx.x == 0) {
            g_xs[r] = e;
        }
    }
}

// Init: out[r][o] = xs[r] * S[o]   (the "+1" part of W = 1 + w')
__global__ void init_out_kernel(float* __restrict__ out) {
    int i = blockIdx.x * 256 + threadIdx.x;
    out[i] = g_xs[i >> 4] * g_S[i & 15];
}

// ---------------------------------------------------------------------------
// Main: 128x128 fp16 HMMA GEMM (K=512), 3-stage cp.async, then
// epilogue: w' = exp(2*gamma*c) - 1 (fp16) and out += xs * (W' @ alpha) via HMMA.
// ---------------------------------------------------------------------------
__global__ __launch_bounds__(128, 3)
void rbf_hmma_kernel(float* __restrict__ out) {
    extern __shared__ __align__(1024) uint8_t smem[];
    const uint32_t sb = smem_u32(smem);

    const int tid    = threadIdx.x;
    const int lane   = tid & 31;
    const int wid    = tid >> 5;
    const int warp_m = wid & 1;
    const int warp_n = wid >> 1;
    const int row0   = blockIdx.x * BM;
    const int j0     = blockIdx.y * BN;

    // ldmatrix per-lane byte offsets within a stage (80B row pitch)
    const uint32_t aoff =
        (uint32_t)(warp_m * 64 + ((lane >> 3) & 1) * 8 + (lane & 7)) * 80
        + (uint32_t)(lane >> 4) * 16;
    const uint32_t boff = OFF_B +
        (uint32_t)(warp_n * 64 + ((lane >> 4) & 1) * 8 + (lane & 7)) * 80
        + (uint32_t)((lane >> 3) & 1) * 16;

    // cp.async fixed row/granule + hoisted global pointers
    const int cprow = tid >> 2;
    const int cpkg  = tid & 3;
    const __half* xsrc = g_Xh + (size_t)(row0 + cprow) * DIM + cpkg * 8;
    const __half* ysrc = g_Yh + (size_t)(j0   + cprow) * DIM + cpkg * 8;
    const uint32_t cpdst = (uint32_t)cprow * 80 + (uint32_t)cpkg * 16;
    const uint32_t ROWSTEP = 32 * DIM;

    // Stage the scaled-alpha tile as fp16 [128 rows][48B pitch]
    {
        const float4* src = (const float4*)(g_as + (size_t)j0 * NOUT);
        #pragma unroll
        for (int i = 0; i < 4; i++) {
            int idx = tid + i * 128;           // 0..511
            int r = idx >> 2, oq = idx & 3;
            float4 a = src[idx];
            __half2 h01 = __floats2half2_rn(a.x, a.y);
            __half2 h23 = __floats2half2_rn(a.z, a.w);
            uint2 u;
            u.x = *(uint32_t*)&h01;
            u.y = *(uint32_t*)&h23;
            *(uint2*)(smem + OFF_ASH + r * 48 + oq * 8) = u;
        }
    }

    // Prologue: prefetch chunks 0..1 into stages 0..1
    #pragma unroll
    for (int p = 0; p < 2; p++) {
        const uint32_t stb = (uint32_t)p * STAGE_BYTES;
        #pragma unroll
        for (int i = 0; i < 4; i++) {
            cp16(sb + stb + cpdst + i * 2560,         xsrc + i * ROWSTEP + p * KT);
            cp16(sb + stb + OFF_B + cpdst + i * 2560, ysrc + i * ROWSTEP + p * KT);
        }
        CP_COMMIT();
    }

    float acc[4][8][4];
    #pragma unroll
    for (int mt = 0; mt < 4; mt++)
        #pragma unroll
        for (int nt = 0; nt < 8; nt++)
            #pragma unroll
            for (int q = 0; q < 4; q++) acc[mt][nt][q] = 0.0f;

    for (int c = 0; c < KCHUNKS; c++) {
        CP_WAIT(1);
        __syncthreads();

        if (c + 2 < KCHUNKS) {
            const uint32_t nstb = (uint32_t)((c + 2) % 3) * STAGE_BYTES;
            const int kb = (c + 2) * KT;
            #pragma unroll
            for (int i = 0; i < 4; i++) {
                cp16(sb + nstb + cpdst + i * 2560,         xsrc + i * ROWSTEP + kb);
                cp16(sb + nstb + OFF_B + cpdst + i * 2560, ysrc + i * ROWSTEP + kb);
            }
        }
        CP_COMMIT();

        const uint32_t stb = (uint32_t)(c % 3) * STAGE_BYTES;
        #pragma unroll
        for (int ks = 0; ks < 2; ks++) {
            uint32_t af[4][4], bf[4][4];
            #pragma unroll
            for (int mt = 0; mt < 4; mt++)
                LDMX4(af[mt], sb + stb + aoff + mt * 1280 + ks * 32);
            #pragma unroll
            for (int nb = 0; nb < 4; nb++)
                LDMX4(bf[nb], sb + stb + boff + nb * 1280 + ks * 32);
            #pragma unroll
            for (int mt = 0; mt < 4; mt++)
                #pragma unroll
                for (int nt = 0; nt < 8; nt++)
                    MMAF16(acc[mt][nt], af[mt],
                           bf[nt >> 1][(nt & 1) * 2],
                           bf[nt >> 1][(nt & 1) * 2 + 1]);
        }
    }

    // ---------------- Epilogue ---------------------------------------------
    // W' = exp(2*gamma*C) - 1 -> fp16 tile Ws[128][WS_PITCH]; then
    // out_tile = W' @ alpha_h via HMMA; out += xs * out_tile (atomics).
    __syncthreads();   // all LDSM of last chunk done before overwriting stages

    #pragma unroll
    for (int mt = 0; mt < 4; mt++) {
        const int m = warp_m * 64 + mt * 16 + (lane >> 2);
        #pragma unroll
        for (int nt = 0; nt < 8; nt++) {
            const int n = warp_n * 64 + nt * 8 + 2 * (lane & 3);
            float w0 = __expf(acc[mt][nt][0] * (2.0f * GAMMA)) - 1.0f;
            float w1 = __expf(acc[mt][nt][1] * (2.0f * GAMMA)) - 1.0f;
            float w2 = __expf(acc[mt][nt][2] * (2.0f * GAMMA)) - 1.0f;
            float w3 = __expf(acc[mt][nt][3] * (2.0f * GAMMA)) - 1.0f;
            *(__half2*)(smem + m * WS_PITCH + n * 2)       = __floats2half2_rn(w0, w1);
            *(__half2*)(smem + (m + 8) * WS_PITCH + n * 2) = __floats2half2_rn(w2, w3);
        }
    }
    __syncthreads();

    // Tensor GEMV: warp w handles rows [32w, 32w+32), all 16 outputs.
    float oa[2][2][4];
    #pragma unroll
    for (int a = 0; a < 2; a++)
        #pragma unroll
        for (int b = 0; b < 2; b++)
            #pragma unroll
            for (int q = 0; q < 4; q++) oa[a][b][q] = 0.0f;

    #pragma unroll
    for (int kt = 0; kt < 8; kt++) {
        uint32_t bfr[4];
        LDMX4T(bfr, sb + OFF_ASH + (uint32_t)(kt * 16 + (lane & 15)) * 48
                    + (uint32_t)(lane >> 4) * 16);
        #pragma unroll
        for (int mt2 = 0; mt2 < 2; mt2++) {
            uint32_t afr[4];
            LDMX4(afr, sb + (uint32_t)(wid * 32 + mt2 * 16 + (lane & 15)) * WS_PITCH
                       + (uint32_t)(lane >> 4) * 16 + kt * 32);
            MMAF16(oa[mt2][0], afr, bfr[0], bfr[1]);
            MMAF16(oa[mt2][1], afr, bfr[2], bfr[3]);
        }
    }

    #pragma unroll
    for (int mt2 = 0; mt2 < 2; mt2++) {
        const int r = row0 + wid * 32 + mt2 * 16 + (lane >> 2);
        const float xs0 = g_xs[r];
        const float xs1 = g_xs[r + 8];
        #pragma unroll
        for (int nt2 = 0; nt2 < 2; nt2++) {
            const int cc = nt2 * 8 + 2 * (lane & 3);
            atomicAdd(&out[(size_t)r * NOUT + cc],           oa[mt2][nt2][0] * xs0);
            atomicAdd(&out[(size_t)r * NOUT + cc + 1],       oa[mt2][nt2][1] * xs0);
            atomicAdd(&out[(size_t)(r + 8) * NOUT + cc],     oa[mt2][nt2][2] * xs1);
            atomicAdd(&out[(size_t)(r + 8) * NOUT + cc + 1], oa[mt2][nt2][3] * xs1);
        }
    }
}

// ---------------------------------------------------------------------------
extern "C" void kernel_launch(void* const* d_in, const int* in_sizes, int n_in,
                              void* d_out, int out_size) {
    const float* X     = (const float*)d_in[0];
    const float* TX    = (const float*)d_in[1];
    const float* alpha = (const float*)d_in[2];
    float* out = (float*)d_out;

    cudaFuncSetAttribute(rbf_hmma_kernel,
                         cudaFuncAttributeMaxDynamicSharedMemorySize, SMEM_BYTES);

    zero_s_kernel<<<1, 32>>>();
    prep_kernel<<<NTEST + NTRAIN, 128>>>(X, TX, alpha);
    init_out_kernel<<<(NTEST * NOUT) / 256, 256>>>(out);
    rbf_hmma_kernel<<<dim3(NTEST / BM, NTRAIN / BN), 128, SMEM_BYTES>>>(out);
}

// round 8
// speedup vs baseline: 9.3571x; 1.0666x over previous
#include <cuda_runtime.h>
#include <cuda_fp16.h>
#include <stdint.h>

// Problem constants
#define GAMMA   0.001f
#define DIM     512
#define NTEST   8192
#define NTRAIN  8192
#define NOUT    16

// Tiling
#define BM      128
#define BN      128
#define KT      64                  // fp16 K per chunk
#define KCHUNKS (DIM / KT)          // 8

// SMEM: stage = A(128 x 144B) + B(128 x 144B) = 36864B, 2 stages
#define PITCH       144
#define TILE_BYTES  (128 * PITCH)            // 18432
#define STAGE_BYTES (2 * TILE_BYTES)         // 36864
#define OFF_B       TILE_BYTES
#define OFF_ASH     (2 * STAGE_BYTES)        // 73728: alpha fp16 128 x 48B
#define SMEM_BYTES  (OFF_ASH + 6144)         // 79872 -> 2 CTAs/SM
#define WS_PITCH    272                      // fp16 W' tile row pitch (epilogue)

// Device scratch
__device__ __half g_Xh[NTEST * DIM];
__device__ __half g_Yh[NTRAIN * DIM];
__device__ float  g_xs[NTEST];           // exp(-gamma*||x||^2)
__device__ float  g_as[NTRAIN * NOUT];   // alpha * exp(-gamma*||y||^2)
__device__ float  g_S[NOUT];             // column sums of g_as

// ---------------------------------------------------------------------------
__device__ __forceinline__ uint32_t smem_u32(const void* p) {
    uint32_t a;
    asm("{ .reg .u64 t; cvta.to.shared.u64 t, %1; cvt.u32.u64 %0, t; }"
        : "=r"(a) : "l"(p));
    return a;
}
__device__ __forceinline__ void cp16(uint32_t dst, const void* src) {
    asm volatile("cp.async.cg.shared.global [%0], [%1], 16;"
                 :: "r"(dst), "l"(src));
}
#define CP_COMMIT() asm volatile("cp.async.commit_group;" ::: "memory")
#define CP_WAIT(n)  asm volatile("cp.async.wait_group %0;" :: "n"(n) : "memory")

#define LDMX4(r, addr) \
    asm volatile("ldmatrix.sync.aligned.m8n8.x4.shared.b16 {%0,%1,%2,%3}, [%4];" \
        : "=r"((r)[0]), "=r"((r)[1]), "=r"((r)[2]), "=r"((r)[3]) : "r"(addr))

#define LDMX4T(r, addr) \
    asm volatile("ldmatrix.sync.aligned.m8n8.x4.trans.shared.b16 {%0,%1,%2,%3}, [%4];" \
        : "=r"((r)[0]), "=r"((r)[1]), "=r"((r)[2]), "=r"((r)[3]) : "r"(addr))

#define MMAF16(c, a, b0, b1) \
    asm volatile("mma.sync.aligned.m16n8k16.row.col.f32.f16.f16.f32 " \
        "{%0,%1,%2,%3}, {%4,%5,%6,%7}, {%8,%9}, {%0,%1,%2,%3};" \
        : "+f"((c)[0]), "+f"((c)[1]), "+f"((c)[2]), "+f"((c)[3]) \
        : "r"((a)[0]), "r"((a)[1]), "r"((a)[2]), "r"((a)[3]), "r"(b0), "r"(b1))

// ---------------------------------------------------------------------------
__global__ void zero_s_kernel() {
    if (threadIdx.x < NOUT) g_S[threadIdx.x] = 0.0f;
}

// Prep: fp32 -> fp16 + norm folding + global alpha column sums.
__global__ void prep_kernel(const float* __restrict__ X,
                            const float* __restrict__ TX,
                            const float* __restrict__ alpha) {
    const int row = blockIdx.x;
    const bool train = (row >= NTEST);
    const int r = train ? row - NTEST : row;
    const float* src = train ? TX + (size_t)r * DIM : X + (size_t)r * DIM;
    __half* dst = train ? g_Yh + (size_t)r * DIM : g_Xh + (size_t)r * DIM;

    float4 v = ((const float4*)src)[threadIdx.x];
    __half2* d2 = (__half2*)dst;
    d2[threadIdx.x * 2]     = __floats2half2_rn(v.x, v.y);
    d2[threadIdx.x * 2 + 1] = __floats2half2_rn(v.z, v.w);

    float s = v.x * v.x + v.y * v.y + v.z * v.z + v.w * v.w;
    #pragma unroll
    for (int off = 16; off > 0; off >>= 1)
        s += __shfl_down_sync(0xffffffffu, s, off);
    __shared__ float red[4];
    if ((threadIdx.x & 31) == 0) red[threadIdx.x >> 5] = s;
    __syncthreads();
    if (threadIdx.x < NOUT) {
        float e = __expf(-GAMMA * (red[0] + red[1] + red[2] + red[3]));
        if (train) {
            float val = alpha[r * NOUT + threadIdx.x] * e;
            g_as[r * NOUT + threadIdx.x] = val;
            atomicAdd(&g_S[threadIdx.x], val);
        } else if (threadIdx.x == 0) {
            g_xs[r] = e;
        }
    }
}

// Init: out[r][o] = xs[r] * S[o]   (the "+1" part of W = 1 + w')
__global__ void init_out_kernel(float* __restrict__ out) {
    int i = blockIdx.x * 256 + threadIdx.x;
    out[i] = g_xs[i >> 4] * g_S[i & 15];
}

// ---------------------------------------------------------------------------
// Main: 128x128 fp16 HMMA GEMM (K=512), KT=64, 2-stage cp.async,
// register-fragment double buffering; epilogue: w'=exp(2g c)-1 fp16, HMMA GEMV.
// ---------------------------------------------------------------------------
__global__ __launch_bounds__(128, 2)
void rbf_hmma_kernel(float* __restrict__ out) {
    extern __shared__ __align__(1024) uint8_t smem[];
    const uint32_t sb = smem_u32(smem);

    const int tid    = threadIdx.x;
    const int lane   = tid & 31;
    const int wid    = tid >> 5;
    const int warp_m = wid & 1;
    const int warp_n = wid >> 1;
    const int row0   = blockIdx.x * BM;
    const int j0     = blockIdx.y * BN;

    // ldmatrix per-lane base byte offsets within a stage (144B pitch)
    const uint32_t aoff =
        (uint32_t)(warp_m * 64 + ((lane >> 3) & 1) * 8 + (lane & 7)) * PITCH
        + (uint32_t)(lane >> 4) * 16;
    const uint32_t boff = OFF_B +
        (uint32_t)(warp_n * 64 + ((lane >> 4) & 1) * 8 + (lane & 7)) * PITCH
        + (uint32_t)((lane >> 3) & 1) * 16;

    // cp.async: thread -> (row tid>>3 (+16*i), granule tid&7); hoisted pointers
    const int cprow = tid >> 3;          // 0..15
    const int cpkg  = tid & 7;           // 16B granule (128B row = 8 granules)
    const __half* xsrc = g_Xh + (size_t)(row0 + cprow) * DIM + cpkg * 8;
    const __half* ysrc = g_Yh + (size_t)(j0   + cprow) * DIM + cpkg * 8;
    const uint32_t cpdst = (uint32_t)cprow * PITCH + (uint32_t)cpkg * 16;
    const uint32_t ROWSTEP = 16 * DIM;   // elements per +16 rows

    // Stage the scaled-alpha tile as fp16 [128 rows][48B pitch]
    {
        const float4* src = (const float4*)(g_as + (size_t)j0 * NOUT);
        #pragma unroll
        for (int i = 0; i < 4; i++) {
            int idx = tid + i * 128;
            int r = idx >> 2, oq = idx & 3;
            float4 a = src[idx];
            __half2 h01 = __floats2half2_rn(a.x, a.y);
            __half2 h23 = __floats2half2_rn(a.z, a.w);
            uint2 u;
            u.x = *(uint32_t*)&h01;
            u.y = *(uint32_t*)&h23;
            *(uint2*)(smem + OFF_ASH + r * 48 + oq * 8) = u;
        }
    }

    // Prologue: fill chunk 0 into stage 0
    #pragma unroll
    for (int i = 0; i < 8; i++) {
        cp16(sb + cpdst + i * (16 * PITCH),         xsrc + i * ROWSTEP);
        cp16(sb + OFF_B + cpdst + i * (16 * PITCH), ysrc + i * ROWSTEP);
    }
    CP_COMMIT();

    float acc[4][8][4];
    #pragma unroll
    for (int mt = 0; mt < 4; mt++)
        #pragma unroll
        for (int nt = 0; nt < 8; nt++)
            #pragma unroll
            for (int q = 0; q < 4; q++) acc[mt][nt][q] = 0.0f;

    uint32_t af[2][4][4], bf[2][4][4];

    #pragma unroll 2
    for (int c = 0; c < KCHUNKS; c++) {
        CP_WAIT(0);          // chunk c landed
        __syncthreads();     // visible to all warps; other stage free

        // Prefetch chunk c+1 into the other stage
        if (c + 1 < KCHUNKS) {
            const uint32_t nstb = (uint32_t)((c + 1) & 1) * STAGE_BYTES;
            const int kb = (c + 1) * KT;
            #pragma unroll
            for (int i = 0; i < 8; i++) {
                cp16(sb + nstb + cpdst + i * (16 * PITCH),
                     xsrc + i * ROWSTEP + kb);
                cp16(sb + nstb + OFF_B + cpdst + i * (16 * PITCH),
                     ysrc + i * ROWSTEP + kb);
            }
        }
        CP_COMMIT();

        const uint32_t stb = (uint32_t)(c & 1) * STAGE_BYTES;

        // Load ks=0 fragments
        #pragma unroll
        for (int mt = 0; mt < 4; mt++)
            LDMX4(af[0][mt], sb + stb + aoff + mt * (16 * PITCH));
        #pragma unroll
        for (int nb = 0; nb < 4; nb++)
            LDMX4(bf[0][nb], sb + stb + boff + nb * (16 * PITCH));

        #pragma unroll
        for (int ks = 0; ks < 4; ks++) {
            const int cur = ks & 1;
            if (ks < 3) {      // prefetch next ks fragments before HMMA block
                const int nxt = cur ^ 1;
                #pragma unroll
                for (int mt = 0; mt < 4; mt++)
                    LDMX4(af[nxt][mt],
                          sb + stb + aoff + mt * (16 * PITCH) + (ks + 1) * 32);
                #pragma unroll
                for (int nb = 0; nb < 4; nb++)
                    LDMX4(bf[nxt][nb],
                          sb + stb + boff + nb * (16 * PITCH) + (ks + 1) * 32);
            }
            #pragma unroll
            for (int mt = 0; mt < 4; mt++)
                #pragma unroll
                for (int nt = 0; nt < 8; nt++)
                    MMAF16(acc[mt][nt], af[cur][mt],
                           bf[cur][nt >> 1][(nt & 1) * 2],
                           bf[cur][nt >> 1][(nt & 1) * 2 + 1]);
        }
    }

    // ---------------- Epilogue ---------------------------------------------
    // W' = exp(2*gamma*C) - 1 -> fp16 Ws[128][WS_PITCH]; out += xs*(W'@alpha)
    __syncthreads();   // all LDSM done before overwriting stage region

    #pragma unroll
    for (int mt = 0; mt < 4; mt++) {
        const int m = warp_m * 64 + mt * 16 + (lane >> 2);
        #pragma unroll
        for (int nt = 0; nt < 8; nt++) {
            const int n = warp_n * 64 + nt * 8 + 2 * (lane & 3);
            float w0 = __expf(acc[mt][nt][0] * (2.0f * GAMMA)) - 1.0f;
            float w1 = __expf(acc[mt][nt][1] * (2.0f * GAMMA)) - 1.0f;
            float w2 = __expf(acc[mt][nt][2] * (2.0f * GAMMA)) - 1.0f;
            float w3 = __expf(acc[mt][nt][3] * (2.0f * GAMMA)) - 1.0f;
            *(__half2*)(smem + m * WS_PITCH + n * 2)       = __floats2half2_rn(w0, w1);
            *(__half2*)(smem + (m + 8) * WS_PITCH + n * 2) = __floats2half2_rn(w2, w3);
        }
    }
    __syncthreads();

    // Tensor GEMV: warp w handles rows [32w, 32w+32), all 16 outputs.
    float oa[2][2][4];
    #pragma unroll
    for (int a = 0; a < 2; a++)
        #pragma unroll
        for (int b = 0; b < 2; b++)
            #pragma unroll
            for (int q = 0; q < 4; q++) oa[a][b][q] = 0.0f;

    #pragma unroll
    for (int kt = 0; kt < 8; kt++) {
        uint32_t bfr[4];
        LDMX4T(bfr, sb + OFF_ASH + (uint32_t)(kt * 16 + (lane & 15)) * 48
                    + (uint32_t)(lane >> 4) * 16);
        #pragma unroll
        for (int mt2 = 0; mt2 < 2; mt2++) {
            uint32_t afr[4];
            LDMX4(afr, sb + (uint32_t)(wid * 32 + mt2 * 16 + (lane & 15)) * WS_PITCH
                       + (uint32_t)(lane >> 4) * 16 + kt * 32);
            MMAF16(oa[mt2][0], afr, bfr[0], bfr[1]);
            MMAF16(oa[mt2][1], afr, bfr[2], bfr[3]);
        }
    }

    #pragma unroll
    for (int mt2 = 0; mt2 < 2; mt2++) {
        const int r = row0 + wid * 32 + mt2 * 16 + (lane >> 2);
        const float xs0 = g_xs[r];
        const float xs1 = g_xs[r + 8];
        #pragma unroll
        for (int nt2 = 0; nt2 < 2; nt2++) {
            const int cc = nt2 * 8 + 2 * (lane & 3);
            atomicAdd(&out[(size_t)r * NOUT + cc],           oa[mt2][nt2][0] * xs0);
            atomicAdd(&out[(size_t)r * NOUT + cc + 1],       oa[mt2][nt2][1] * xs0);
            atomicAdd(&out[(size_t)(r + 8) * NOUT + cc],     oa[mt2][nt2][2] * xs1);
            atomicAdd(&out[(size_t)(r + 8) * NOUT + cc + 1], oa[mt2][nt2][3] * xs1);
        }
    }
}

// ---------------------------------------------------------------------------
extern "C" void kernel_launch(void* const* d_in, const int* in_sizes, int n_in,
                              void* d_out, int out_size) {
    const float* X     = (const float*)d_in[0];
    const float* TX    = (const float*)d_in[1];
    const float* alpha = (const float*)d_in[2];
    float* out = (float*)d_out;

    cudaFuncSetAttribute(rbf_hmma_kernel,
                         cudaFuncAttributeMaxDynamicSharedMemorySize, SMEM_BYTES);

    zero_s_kernel<<<1, 32>>>();
    prep_kernel<<<NTEST + NTRAIN, 128>>>(X, TX, alpha);
    init_out_kernel<<<(NTEST * NOUT) / 256, 256>>>(out);
    rbf_hmma_kernel<<<dim3(NTEST / BM, NTRAIN / BN), 128, SMEM_BYTES>>>(out);
}